// round 4
// baseline (speedup 1.0000x reference)
#include <cuda_runtime.h>
#include <math.h>

// ---------------------------------------------------------------------------
// Shapes (fixed by the problem)
// ---------------------------------------------------------------------------
#define BATCH 8
#define SEQ   1024
#define CH    1024
#define HID   4096
#define NHEAD 16
#define HDIM  64          // CH / NHEAD
#define ROWS  (BATCH*SEQ) // 8192

// ---------------------------------------------------------------------------
// Scratch (device globals: no runtime allocation allowed)
// ---------------------------------------------------------------------------
__device__ float g_lnq [ROWS*CH];
__device__ float g_lnkv[ROWS*CH];
__device__ float g_q   [ROWS*CH];
__device__ float g_k   [ROWS*CH];
__device__ float g_v   [ROWS*CH];
__device__ float g_o   [ROWS*CH];
__device__ float g_x   [ROWS*CH];
__device__ float g_h   [ROWS*HID];

// ---------------------------------------------------------------------------
// LayerNorm: one block per row, C = 1024 fixed
// ---------------------------------------------------------------------------
__global__ void __launch_bounds__(256)
ln_kernel(const float* __restrict__ x, const float* __restrict__ g,
          const float* __restrict__ b, float* __restrict__ y)
{
    const int row = blockIdx.x;
    const int t   = threadIdx.x;
    const float4 xv = reinterpret_cast<const float4*>(x + (size_t)row*CH)[t];

    float s  = xv.x + xv.y + xv.z + xv.w;
    float ss = xv.x*xv.x + xv.y*xv.y + xv.z*xv.z + xv.w*xv.w;
    #pragma unroll
    for (int o = 16; o; o >>= 1) {
        s  += __shfl_xor_sync(0xffffffffu, s,  o);
        ss += __shfl_xor_sync(0xffffffffu, ss, o);
    }
    __shared__ float sh_s[8], sh_ss[8];
    if ((t & 31) == 0) { sh_s[t >> 5] = s; sh_ss[t >> 5] = ss; }
    __syncthreads();
    float ts = 0.f, tss = 0.f;
    #pragma unroll
    for (int i = 0; i < 8; i++) { ts += sh_s[i]; tss += sh_ss[i]; }

    const float mean = ts * (1.0f / CH);
    const float var  = tss * (1.0f / CH) - mean * mean;
    const float rstd = rsqrtf(var + 1e-5f);

    const float4 gv = reinterpret_cast<const float4*>(g)[t];
    const float4 bv = reinterpret_cast<const float4*>(b)[t];
    float4 out;
    out.x = (xv.x - mean) * rstd * gv.x + bv.x;
    out.y = (xv.y - mean) * rstd * gv.y + bv.y;
    out.z = (xv.z - mean) * rstd * gv.z + bv.z;
    out.w = (xv.w - mean) * rstd * gv.w + bv.w;
    reinterpret_cast<float4*>(y + (size_t)row*CH)[t] = out;
}

// ---------------------------------------------------------------------------
// SGEMM: C[M,N] = A[M,K] @ B[K,N] (+bias)(+gelu)(+resid), row-major.
// 128x128 block tile, BK=8, 256 threads, 8x8 per thread.
// Double-buffered shared memory: one __syncthreads per K-tile, global loads
// for tile i+1 issued before computing tile i.
// OP: 0 = none, 1 = +bias, 2 = +bias then exact GELU
// ---------------------------------------------------------------------------
template<int OP, bool HASRES>
__global__ void __launch_bounds__(256)
sgemm_kernel(const float* __restrict__ A, const float* __restrict__ B,
             float* __restrict__ C, const float* __restrict__ bias,
             const float* __restrict__ resid, int M, int N, int K)
{
    __shared__ float As[2][8][128];
    __shared__ float Bs[2][8][128];

    const int bx = blockIdx.x;   // N tile
    const int by = blockIdx.y;   // M tile
    const int t  = threadIdx.x;
    const int tx = t & 15;
    const int ty = t >> 4;

    const float* Ablk = A + (size_t)(by * 128) * K;
    const float* Bblk = B + bx * 128;

    const int arow = t >> 1, acol = (t & 1) * 4;
    const int brow = t >> 5, bcol = (t & 31) * 4;

    float acc[8][8];
    #pragma unroll
    for (int i = 0; i < 8; i++)
        #pragma unroll
        for (int j = 0; j < 8; j++) acc[i][j] = 0.f;

    // preload tile 0 into buffer 0
    {
        float4 av = *reinterpret_cast<const float4*>(Ablk + (size_t)arow * K + acol);
        float4 bv = *reinterpret_cast<const float4*>(Bblk + (size_t)brow * N + bcol);
        As[0][acol + 0][arow] = av.x;
        As[0][acol + 1][arow] = av.y;
        As[0][acol + 2][arow] = av.z;
        As[0][acol + 3][arow] = av.w;
        *reinterpret_cast<float4*>(&Bs[0][brow][bcol]) = bv;
    }
    __syncthreads();

    for (int k0 = 0; k0 < K; k0 += 8) {
        const int buf = (k0 >> 3) & 1;

        // issue next tile's global loads early (overlap with compute)
        float4 av2, bv2;
        const bool more = (k0 + 8) < K;
        if (more) {
            av2 = *reinterpret_cast<const float4*>(Ablk + (size_t)arow * K + (k0 + 8) + acol);
            bv2 = *reinterpret_cast<const float4*>(Bblk + (size_t)(k0 + 8 + brow) * N + bcol);
        }

        #pragma unroll
        for (int k = 0; k < 8; k++) {
            float a[8], b2[8];
            *reinterpret_cast<float4*>(&a[0])  = *reinterpret_cast<const float4*>(&As[buf][k][ty * 8]);
            *reinterpret_cast<float4*>(&a[4])  = *reinterpret_cast<const float4*>(&As[buf][k][ty * 8 + 4]);
            *reinterpret_cast<float4*>(&b2[0]) = *reinterpret_cast<const float4*>(&Bs[buf][k][tx * 8]);
            *reinterpret_cast<float4*>(&b2[4]) = *reinterpret_cast<const float4*>(&Bs[buf][k][tx * 8 + 4]);
            #pragma unroll
            for (int i = 0; i < 8; i++)
                #pragma unroll
                for (int j = 0; j < 8; j++)
                    acc[i][j] = fmaf(a[i], b2[j], acc[i][j]);
        }

        if (more) {
            const int nbuf = buf ^ 1;
            As[nbuf][acol + 0][arow] = av2.x;
            As[nbuf][acol + 1][arow] = av2.y;
            As[nbuf][acol + 2][arow] = av2.z;
            As[nbuf][acol + 3][arow] = av2.w;
            *reinterpret_cast<float4*>(&Bs[nbuf][brow][bcol]) = bv2;
        }
        __syncthreads();
    }

    const int row0 = by * 128 + ty * 8;
    const int col0 = bx * 128 + tx * 8;
    float bvals[8];
    if (OP >= 1) {
        #pragma unroll
        for (int j = 0; j < 8; j++) bvals[j] = bias[col0 + j];
    }
    #pragma unroll
    for (int i = 0; i < 8; i++) {
        const size_t off = (size_t)(row0 + i) * N + col0;
        #pragma unroll
        for (int j = 0; j < 8; j++) {
            float v = acc[i][j];
            if (OP >= 1) v += bvals[j];
            if (OP == 2) v = 0.5f * v * (1.0f + erff(v * 0.70710678118654752f));
            if (HASRES)  v += resid[off + j];
            C[off + j] = v;
        }
    }
}

// ---------------------------------------------------------------------------
// Flash-style attention: grid (SEQ/64, NHEAD, BATCH), 256 threads.
// Each block: 64 query rows of one (b,h). thread = (row r = tid/4, sub = tid%4);
// sub owns 16 key-cols of S and 16 d-cols of O.
// Dynamic smem: Qs/Ks/Vs/Ss, each 64 x 65 floats.
// ---------------------------------------------------------------------------
#define ATT_STRIDE 65
#define ATT_SMEM   (4 * 64 * ATT_STRIDE * sizeof(float))

__global__ void __launch_bounds__(256)
attn_kernel(const float* __restrict__ Q, const float* __restrict__ K,
            const float* __restrict__ V, float* __restrict__ O)
{
    extern __shared__ float sm[];
    float* Qs = sm;
    float* Ks = Qs + 64 * ATT_STRIDE;
    float* Vs = Ks + 64 * ATT_STRIDE;
    float* Ss = Vs + 64 * ATT_STRIDE;

    const int q0 = blockIdx.x * 64;
    const int h  = blockIdx.y;
    const int b  = blockIdx.z;
    const int tid = threadIdx.x;
    const int r   = tid >> 2;
    const int sub = tid & 3;

    // load Q tile: 64 rows x 64 cols (head slice)
    #pragma unroll
    for (int i = 0; i < 4; i++) {
        int idx = tid + i * 256;          // 1024 float4s
        int row = idx >> 4, c4 = idx & 15;
        float4 v4 = *reinterpret_cast<const float4*>(
            Q + ((size_t)(b * SEQ + q0 + row)) * CH + h * HDIM + c4 * 4);
        float* d = &Qs[row * ATT_STRIDE + c4 * 4];
        d[0] = v4.x; d[1] = v4.y; d[2] = v4.z; d[3] = v4.w;
    }

    float m = -1e30f, l = 0.f;
    float acc[16];
    #pragma unroll
    for (int c = 0; c < 16; c++) acc[c] = 0.f;

    for (int t0 = 0; t0 < SEQ; t0 += 64) {
        __syncthreads();   // protect prev-iter shared reads (also covers Q-load on iter 0)
        #pragma unroll
        for (int i = 0; i < 4; i++) {
            int idx = tid + i * 256;
            int row = idx >> 4, c4 = idx & 15;
            size_t goff = ((size_t)(b * SEQ + t0 + row)) * CH + h * HDIM + c4 * 4;
            float4 kv = *reinterpret_cast<const float4*>(K + goff);
            float4 vv = *reinterpret_cast<const float4*>(V + goff);
            float* dk = &Ks[row * ATT_STRIDE + c4 * 4];
            float* dv = &Vs[row * ATT_STRIDE + c4 * 4];
            dk[0] = kv.x; dk[1] = kv.y; dk[2] = kv.z; dk[3] = kv.w;
            dv[0] = vv.x; dv[1] = vv.y; dv[2] = vv.z; dv[3] = vv.w;
        }
        __syncthreads();

        // S = (Q K^T) * scale for my 16 key-cols
        float s[16];
        float mloc = -1e30f;
        #pragma unroll
        for (int jj = 0; jj < 16; jj++) {
            const float* qrow = &Qs[r * ATT_STRIDE];
            const float* krow = &Ks[(sub * 16 + jj) * ATT_STRIDE];
            float d0 = 0.f;
            #pragma unroll
            for (int k = 0; k < 64; k++) d0 = fmaf(qrow[k], krow[k], d0);
            s[jj] = d0 * 0.125f;            // 1/sqrt(64)
            mloc = fmaxf(mloc, s[jj]);
        }
        // row max across 4-lane group
        mloc = fmaxf(mloc, __shfl_xor_sync(0xffffffffu, mloc, 1));
        mloc = fmaxf(mloc, __shfl_xor_sync(0xffffffffu, mloc, 2));
        const float mnew  = fmaxf(m, mloc);
        const float alpha = __expf(m - mnew);
        l *= alpha;
        #pragma unroll
        for (int c = 0; c < 16; c++) acc[c] *= alpha;

        float ls = 0.f;
        #pragma unroll
        for (int jj = 0; jj < 16; jj++) {
            float p = __expf(s[jj] - mnew);
            ls += p;
            Ss[r * ATT_STRIDE + sub * 16 + jj] = p;
        }
        l += ls;
        m = mnew;
        __syncthreads();

        // O += P @ V  (my 16 d-cols)
        #pragma unroll
        for (int jj = 0; jj < 64; jj++) {
            const float p = Ss[r * ATT_STRIDE + jj];
            const float* vrow = &Vs[jj * ATT_STRIDE + sub * 16];
            #pragma unroll
            for (int c = 0; c < 16; c++) acc[c] = fmaf(p, vrow[c], acc[c]);
        }
    }

    // total l across 4-lane group, normalize, write out (B,N,H*d) layout
    l += __shfl_xor_sync(0xffffffffu, l, 1);
    l += __shfl_xor_sync(0xffffffffu, l, 2);
    const float inv = 1.0f / l;
    float* out = O + ((size_t)(b * SEQ + q0 + r)) * CH + h * HDIM + sub * 16;
    #pragma unroll
    for (int c = 0; c < 16; c++) out[c] = acc[c] * inv;
}

// ---------------------------------------------------------------------------
// Host-side orchestration
// ---------------------------------------------------------------------------
static void run_gemm_plain(const float* A, const float* B, float* C, int M, int N, int K)
{
    dim3 grid(N / 128, M / 128);
    sgemm_kernel<0, false><<<grid, 256>>>(A, B, C, nullptr, nullptr, M, N, K);
}
static void run_gemm_bias_res(const float* A, const float* B, float* C,
                              const float* bias, const float* resid, int M, int N, int K)
{
    dim3 grid(N / 128, M / 128);
    sgemm_kernel<1, true><<<grid, 256>>>(A, B, C, bias, resid, M, N, K);
}
static void run_gemm_bias_gelu(const float* A, const float* B, float* C,
                               const float* bias, int M, int N, int K)
{
    dim3 grid(N / 128, M / 128);
    sgemm_kernel<2, false><<<grid, 256>>>(A, B, C, bias, nullptr, M, N, K);
}

extern "C" void kernel_launch(void* const* d_in, const int* in_sizes, int n_in,
                              void* d_out, int out_size)
{
    // inputs (metadata order)
    const float* x1    = (const float*)d_in[0];
    const float* x2    = (const float*)d_in[1];
    const float* x3    = (const float*)d_in[2];
    const float* ln11g = (const float*)d_in[3];
    const float* ln11b = (const float*)d_in[4];
    const float* ln12g = (const float*)d_in[5];
    const float* ln12b = (const float*)d_in[6];
    const float* ln21g = (const float*)d_in[7];
    const float* ln21b = (const float*)d_in[8];
    const float* ln23g = (const float*)d_in[9];
    const float* ln23b = (const float*)d_in[10];
    const float* ln2g  = (const float*)d_in[11];
    const float* ln2b  = (const float*)d_in[12];
    const float* a1wq  = (const float*)d_in[13];
    const float* a1wk  = (const float*)d_in[14];
    const float* a1wv  = (const float*)d_in[15];
    const float* a1wp  = (const float*)d_in[16];
    const float* a1bp  = (const float*)d_in[17];
    const float* a2wq  = (const float*)d_in[18];
    const float* a2wk  = (const float*)d_in[19];
    const float* a2wv  = (const float*)d_in[20];
    const float* a2wp  = (const float*)d_in[21];
    const float* a2bp  = (const float*)d_in[22];
    const float* fc1w  = (const float*)d_in[23];
    const float* fc1b  = (const float*)d_in[24];
    const float* fc2w  = (const float*)d_in[25];
    const float* fc2b  = (const float*)d_in[26];
    float* out = (float*)d_out;

    float *lnq, *lnkv, *q, *k, *v, *o, *x, *hbuf;
    cudaGetSymbolAddress((void**)&lnq,  g_lnq);
    cudaGetSymbolAddress((void**)&lnkv, g_lnkv);
    cudaGetSymbolAddress((void**)&q,    g_q);
    cudaGetSymbolAddress((void**)&k,    g_k);
    cudaGetSymbolAddress((void**)&v,    g_v);
    cudaGetSymbolAddress((void**)&o,    g_o);
    cudaGetSymbolAddress((void**)&x,    g_x);
    cudaGetSymbolAddress((void**)&hbuf, g_h);

    cudaFuncSetAttribute(attn_kernel, cudaFuncAttributeMaxDynamicSharedMemorySize,
                         (int)ATT_SMEM);

    const dim3 attn_grid(SEQ / 64, NHEAD, BATCH);

    // ---- branch 1: cross-attn(LN(x1), LN(x2)) ----
    ln_kernel<<<ROWS, 256>>>(x1, ln11g, ln11b, lnq);
    ln_kernel<<<ROWS, 256>>>(x2, ln12g, ln12b, lnkv);
    run_gemm_plain(lnq,  a1wq, q, ROWS, CH, CH);
    run_gemm_plain(lnkv, a1wk, k, ROWS, CH, CH);
    run_gemm_plain(lnkv, a1wv, v, ROWS, CH, CH);
    attn_kernel<<<attn_grid, 256, ATT_SMEM>>>(q, k, v, o);
    run_gemm_bias_res(o, a1wp, x, a1bp, x1, ROWS, CH, CH);   // x = x1 + br1

    // ---- branch 2: cross-attn(LN(x1), LN(x3)) ----
    ln_kernel<<<ROWS, 256>>>(x1, ln21g, ln21b, lnq);
    ln_kernel<<<ROWS, 256>>>(x3, ln23g, ln23b, lnkv);
    run_gemm_plain(lnq,  a2wq, q, ROWS, CH, CH);
    run_gemm_plain(lnkv, a2wk, k, ROWS, CH, CH);
    run_gemm_plain(lnkv, a2wv, v, ROWS, CH, CH);
    attn_kernel<<<attn_grid, 256, ATT_SMEM>>>(q, k, v, o);
    run_gemm_bias_res(o, a2wp, x, a2bp, x, ROWS, CH, CH);    // x += br2 (in-place resid)

    // ---- MLP ----
    ln_kernel<<<ROWS, 256>>>(x, ln2g, ln2b, lnq);
    run_gemm_bias_gelu(lnq, fc1w, hbuf, fc1b, ROWS, HID, CH);   // h = gelu(y@fc1+b1)
    run_gemm_bias_res(hbuf, fc2w, out, fc2b, x, ROWS, CH, HID); // out = x + h@fc2+b2
}

// round 6
// speedup vs baseline: 1.3684x; 1.3684x over previous
#include <cuda_runtime.h>
#include <math.h>

// ---------------------------------------------------------------------------
// Shapes (fixed by the problem)
// ---------------------------------------------------------------------------
#define BATCH 8
#define SEQ   1024
#define CH    1024
#define HID   4096
#define NHEAD 16
#define HDIM  64          // CH / NHEAD
#define ROWS  (BATCH*SEQ) // 8192

// ---------------------------------------------------------------------------
// Scratch (device globals: no runtime allocation allowed)
// ---------------------------------------------------------------------------
__device__ float g_lnq [ROWS*CH];
__device__ float g_lnkv[ROWS*CH];
__device__ float g_q   [ROWS*CH];
__device__ float g_k   [ROWS*CH];
__device__ float g_v   [ROWS*CH];
__device__ float g_o   [ROWS*CH];
__device__ float g_x   [ROWS*CH];
__device__ float g_h   [ROWS*HID];

// ---------------------------------------------------------------------------
// LayerNorm: one block per row, C = 1024 fixed
// ---------------------------------------------------------------------------
__global__ void __launch_bounds__(256)
ln_kernel(const float* __restrict__ x, const float* __restrict__ g,
          const float* __restrict__ b, float* __restrict__ y)
{
    const int row = blockIdx.x;
    const int t   = threadIdx.x;
    const float4 xv = reinterpret_cast<const float4*>(x + (size_t)row*CH)[t];

    float s  = xv.x + xv.y + xv.z + xv.w;
    float ss = xv.x*xv.x + xv.y*xv.y + xv.z*xv.z + xv.w*xv.w;
    #pragma unroll
    for (int o = 16; o; o >>= 1) {
        s  += __shfl_xor_sync(0xffffffffu, s,  o);
        ss += __shfl_xor_sync(0xffffffffu, ss, o);
    }
    __shared__ float sh_s[8], sh_ss[8];
    if ((t & 31) == 0) { sh_s[t >> 5] = s; sh_ss[t >> 5] = ss; }
    __syncthreads();
    float ts = 0.f, tss = 0.f;
    #pragma unroll
    for (int i = 0; i < 8; i++) { ts += sh_s[i]; tss += sh_ss[i]; }

    const float mean = ts * (1.0f / CH);
    const float var  = tss * (1.0f / CH) - mean * mean;
    const float rstd = rsqrtf(var + 1e-5f);

    const float4 gv = reinterpret_cast<const float4*>(g)[t];
    const float4 bv = reinterpret_cast<const float4*>(b)[t];
    float4 out;
    out.x = (xv.x - mean) * rstd * gv.x + bv.x;
    out.y = (xv.y - mean) * rstd * gv.y + bv.y;
    out.z = (xv.z - mean) * rstd * gv.z + bv.z;
    out.w = (xv.w - mean) * rstd * gv.w + bv.w;
    reinterpret_cast<float4*>(y + (size_t)row*CH)[t] = out;
}

// ---------------------------------------------------------------------------
// TF32 tensor-core GEMM: C[M,N] = A[M,K] @ B[K,N] (+bias)(+gelu)(+resid).
// 128x128 block tile, BK=16, 256 threads (8 warps, 2x4), each warp 64x32 via
// 4x4 grid of mma.sync.m16n8k8.tf32. Double-buffered smem, fp32 accumulate.
// OP: 0 = none, 1 = +bias, 2 = +bias then exact GELU
// ---------------------------------------------------------------------------
#define AS_STRIDE 18    // 16 + 2 pad
#define BS_STRIDE 136   // 128 + 8 pad -> conflict-free B-fragment loads

__device__ __forceinline__ unsigned f2tf32(float f) {
    unsigned r;
    asm("cvt.rna.tf32.f32 %0, %1;" : "=r"(r) : "f"(f));
    return r;
}

__device__ __forceinline__ void mma_tf32(float* d,
                                         const unsigned* a, const unsigned* b) {
    asm("mma.sync.aligned.m16n8k8.row.col.f32.tf32.tf32.f32 "
        "{%0,%1,%2,%3}, {%4,%5,%6,%7}, {%8,%9}, {%0,%1,%2,%3};"
        : "+f"(d[0]), "+f"(d[1]), "+f"(d[2]), "+f"(d[3])
        : "r"(a[0]), "r"(a[1]), "r"(a[2]), "r"(a[3]), "r"(b[0]), "r"(b[1]));
}

template<int OP, bool HASRES>
__global__ void __launch_bounds__(256, 2)
gemm_tf32_kernel(const float* __restrict__ A, const float* __restrict__ B,
                 float* __restrict__ C, const float* __restrict__ bias,
                 const float* __restrict__ resid, int M, int N, int K)
{
    __shared__ unsigned As[2][128][AS_STRIDE];
    __shared__ unsigned Bs[2][16][BS_STRIDE];

    const int t    = threadIdx.x;
    const int warp = t >> 5;
    const int lane = t & 31;
    const int g    = lane >> 2;      // 0..7
    const int q    = lane & 3;       // 0..3
    const int wm   = (warp >> 2) * 64;   // 0 / 64
    const int wn   = (warp & 3) * 32;    // 0/32/64/96

    const int bx = blockIdx.x;  // N tile
    const int by = blockIdx.y;  // M tile
    const float* Ablk = A + (size_t)(by * 128) * K;
    const float* Bblk = B + bx * 128;

    // loader coordinates
    const int a_row = t >> 2;            // 0..63 (and +64 for second half)
    const int a_col = (t & 3) * 4;       // 0,4,8,12
    const int b_row = t >> 5;            // 0..7 (and +8)
    const int b_col = (t & 31) * 4;      // 0..124

    float acc[4][4][4];
    #pragma unroll
    for (int f = 0; f < 4; f++)
        #pragma unroll
        for (int j = 0; j < 4; j++)
            #pragma unroll
            for (int r = 0; r < 4; r++) acc[f][j][r] = 0.f;

    // ---- preload tile 0 into buffer 0 ----
    {
        float4 av0 = *reinterpret_cast<const float4*>(Ablk + (size_t)a_row * K + a_col);
        float4 av1 = *reinterpret_cast<const float4*>(Ablk + (size_t)(a_row + 64) * K + a_col);
        float4 bv0 = *reinterpret_cast<const float4*>(Bblk + (size_t)b_row * N + b_col);
        float4 bv1 = *reinterpret_cast<const float4*>(Bblk + (size_t)(b_row + 8) * N + b_col);
        unsigned* pa0 = &As[0][a_row][a_col];
        pa0[0]=f2tf32(av0.x); pa0[1]=f2tf32(av0.y); pa0[2]=f2tf32(av0.z); pa0[3]=f2tf32(av0.w);
        unsigned* pa1 = &As[0][a_row + 64][a_col];
        pa1[0]=f2tf32(av1.x); pa1[1]=f2tf32(av1.y); pa1[2]=f2tf32(av1.z); pa1[3]=f2tf32(av1.w);
        unsigned* pb0 = &Bs[0][b_row][b_col];
        pb0[0]=f2tf32(bv0.x); pb0[1]=f2tf32(bv0.y); pb0[2]=f2tf32(bv0.z); pb0[3]=f2tf32(bv0.w);
        unsigned* pb1 = &Bs[0][b_row + 8][b_col];
        pb1[0]=f2tf32(bv1.x); pb1[1]=f2tf32(bv1.y); pb1[2]=f2tf32(bv1.z); pb1[3]=f2tf32(bv1.w);
    }
    __syncthreads();

    const int ktiles = K >> 4;
    for (int kt = 0; kt < ktiles; kt++) {
        const int buf  = kt & 1;
        const bool more = (kt + 1) < ktiles;

        // prefetch next tile's globals into registers
        float4 av0, av1, bv0, bv1;
        if (more) {
            const int k0 = (kt + 1) << 4;
            av0 = *reinterpret_cast<const float4*>(Ablk + (size_t)a_row * K + k0 + a_col);
            av1 = *reinterpret_cast<const float4*>(Ablk + (size_t)(a_row + 64) * K + k0 + a_col);
            bv0 = *reinterpret_cast<const float4*>(Bblk + (size_t)(k0 + b_row) * N + b_col);
            bv1 = *reinterpret_cast<const float4*>(Bblk + (size_t)(k0 + 8 + b_row) * N + b_col);
        }

        // compute: two k8 steps
        #pragma unroll
        for (int s = 0; s < 2; s++) {
            const int k8 = s * 8;
            unsigned af[4][4];
            #pragma unroll
            for (int f = 0; f < 4; f++) {
                const int m0 = wm + f * 16;
                af[f][0] = As[buf][m0 + g    ][k8 + q];
                af[f][1] = As[buf][m0 + g + 8][k8 + q];
                af[f][2] = As[buf][m0 + g    ][k8 + q + 4];
                af[f][3] = As[buf][m0 + g + 8][k8 + q + 4];
            }
            unsigned bf[4][2];
            #pragma unroll
            for (int j = 0; j < 4; j++) {
                const int n0 = wn + j * 8 + g;
                bf[j][0] = Bs[buf][k8 + q    ][n0];
                bf[j][1] = Bs[buf][k8 + q + 4][n0];
            }
            #pragma unroll
            for (int f = 0; f < 4; f++)
                #pragma unroll
                for (int j = 0; j < 4; j++)
                    mma_tf32(acc[f][j], af[f], bf[j]);
        }

        if (more) {
            const int nbuf = buf ^ 1;
            unsigned* pa0 = &As[nbuf][a_row][a_col];
            pa0[0]=f2tf32(av0.x); pa0[1]=f2tf32(av0.y); pa0[2]=f2tf32(av0.z); pa0[3]=f2tf32(av0.w);
            unsigned* pa1 = &As[nbuf][a_row + 64][a_col];
            pa1[0]=f2tf32(av1.x); pa1[1]=f2tf32(av1.y); pa1[2]=f2tf32(av1.z); pa1[3]=f2tf32(av1.w);
            unsigned* pb0 = &Bs[nbuf][b_row][b_col];
            pb0[0]=f2tf32(bv0.x); pb0[1]=f2tf32(bv0.y); pb0[2]=f2tf32(bv0.z); pb0[3]=f2tf32(bv0.w);
            unsigned* pb1 = &Bs[nbuf][b_row + 8][b_col];
            pb1[0]=f2tf32(bv1.x); pb1[1]=f2tf32(bv1.y); pb1[2]=f2tf32(bv1.z); pb1[3]=f2tf32(bv1.w);
        }
        __syncthreads();
    }

    // ---- epilogue ----
    #pragma unroll
    for (int f = 0; f < 4; f++) {
        const int r0 = by * 128 + wm + f * 16 + g;
        #pragma unroll
        for (int j = 0; j < 4; j++) {
            const int c0 = bx * 128 + wn + j * 8 + 2 * q;
            float v00 = acc[f][j][0], v01 = acc[f][j][1];
            float v10 = acc[f][j][2], v11 = acc[f][j][3];
            if (OP >= 1) {
                const float b0 = bias[c0], b1 = bias[c0 + 1];
                v00 += b0; v01 += b1; v10 += b0; v11 += b1;
            }
            if (OP == 2) {
                v00 = 0.5f * v00 * (1.0f + erff(v00 * 0.70710678118654752f));
                v01 = 0.5f * v01 * (1.0f + erff(v01 * 0.70710678118654752f));
                v10 = 0.5f * v10 * (1.0f + erff(v10 * 0.70710678118654752f));
                v11 = 0.5f * v11 * (1.0f + erff(v11 * 0.70710678118654752f));
            }
            const size_t off0 = (size_t)r0 * N + c0;
            const size_t off1 = (size_t)(r0 + 8) * N + c0;
            if (HASRES) {
                const float2 rr0 = *reinterpret_cast<const float2*>(resid + off0);
                const float2 rr1 = *reinterpret_cast<const float2*>(resid + off1);
                v00 += rr0.x; v01 += rr0.y; v10 += rr1.x; v11 += rr1.y;
            }
            float2 w0; w0.x = v00; w0.y = v01;
            float2 w1; w1.x = v10; w1.y = v11;
            *reinterpret_cast<float2*>(C + off0) = w0;
            *reinterpret_cast<float2*>(C + off1) = w1;
        }
    }
}

// ---------------------------------------------------------------------------
// Flash-style attention: grid (SEQ/64, NHEAD, BATCH), 256 threads.
// ---------------------------------------------------------------------------
#define ATT_STRIDE 65
#define ATT_SMEM   (4 * 64 * ATT_STRIDE * sizeof(float))

__global__ void __launch_bounds__(256)
attn_kernel(const float* __restrict__ Q, const float* __restrict__ K,
            const float* __restrict__ V, float* __restrict__ O)
{
    extern __shared__ float sm[];
    float* Qs = sm;
    float* Ks = Qs + 64 * ATT_STRIDE;
    float* Vs = Ks + 64 * ATT_STRIDE;
    float* Ss = Vs + 64 * ATT_STRIDE;

    const int q0 = blockIdx.x * 64;
    const int h  = blockIdx.y;
    const int b  = blockIdx.z;
    const int tid = threadIdx.x;
    const int r   = tid >> 2;
    const int sub = tid & 3;

    #pragma unroll
    for (int i = 0; i < 4; i++) {
        int idx = tid + i * 256;
        int row = idx >> 4, c4 = idx & 15;
        float4 v4 = *reinterpret_cast<const float4*>(
            Q + ((size_t)(b * SEQ + q0 + row)) * CH + h * HDIM + c4 * 4);
        float* d = &Qs[row * ATT_STRIDE + c4 * 4];
        d[0] = v4.x; d[1] = v4.y; d[2] = v4.z; d[3] = v4.w;
    }

    float m = -1e30f, l = 0.f;
    float acc[16];
    #pragma unroll
    for (int c = 0; c < 16; c++) acc[c] = 0.f;

    for (int t0 = 0; t0 < SEQ; t0 += 64) {
        __syncthreads();
        #pragma unroll
        for (int i = 0; i < 4; i++) {
            int idx = tid + i * 256;
            int row = idx >> 4, c4 = idx & 15;
            size_t goff = ((size_t)(b * SEQ + t0 + row)) * CH + h * HDIM + c4 * 4;
            float4 kv = *reinterpret_cast<const float4*>(K + goff);
            float4 vv = *reinterpret_cast<const float4*>(V + goff);
            float* dk = &Ks[row * ATT_STRIDE + c4 * 4];
            float* dv = &Vs[row * ATT_STRIDE + c4 * 4];
            dk[0] = kv.x; dk[1] = kv.y; dk[2] = kv.z; dk[3] = kv.w;
            dv[0] = vv.x; dv[1] = vv.y; dv[2] = vv.z; dv[3] = vv.w;
        }
        __syncthreads();

        float s[16];
        float mloc = -1e30f;
        #pragma unroll
        for (int jj = 0; jj < 16; jj++) {
            const float* qrow = &Qs[r * ATT_STRIDE];
            const float* krow = &Ks[(sub * 16 + jj) * ATT_STRIDE];
            float d0 = 0.f;
            #pragma unroll
            for (int k = 0; k < 64; k++) d0 = fmaf(qrow[k], krow[k], d0);
            s[jj] = d0 * 0.125f;
            mloc = fmaxf(mloc, s[jj]);
        }
        mloc = fmaxf(mloc, __shfl_xor_sync(0xffffffffu, mloc, 1));
        mloc = fmaxf(mloc, __shfl_xor_sync(0xffffffffu, mloc, 2));
        const float mnew  = fmaxf(m, mloc);
        const float alpha = __expf(m - mnew);
        l *= alpha;
        #pragma unroll
        for (int c = 0; c < 16; c++) acc[c] *= alpha;

        float ls = 0.f;
        #pragma unroll
        for (int jj = 0; jj < 16; jj++) {
            float p = __expf(s[jj] - mnew);
            ls += p;
            Ss[r * ATT_STRIDE + sub * 16 + jj] = p;
        }
        l += ls;
        m = mnew;
        __syncthreads();

        #pragma unroll
        for (int jj = 0; jj < 64; jj++) {
            const float p = Ss[r * ATT_STRIDE + jj];
            const float* vrow = &Vs[jj * ATT_STRIDE + sub * 16];
            #pragma unroll
            for (int c = 0; c < 16; c++) acc[c] = fmaf(p, vrow[c], acc[c]);
        }
    }

    l += __shfl_xor_sync(0xffffffffu, l, 1);
    l += __shfl_xor_sync(0xffffffffu, l, 2);
    const float inv = 1.0f / l;
    float* out = O + ((size_t)(b * SEQ + q0 + r)) * CH + h * HDIM + sub * 16;
    #pragma unroll
    for (int c = 0; c < 16; c++) out[c] = acc[c] * inv;
}

// ---------------------------------------------------------------------------
// Host-side orchestration
// ---------------------------------------------------------------------------
static void run_gemm_plain(const float* A, const float* B, float* C, int M, int N, int K)
{
    dim3 grid(N / 128, M / 128);
    gemm_tf32_kernel<0, false><<<grid, 256>>>(A, B, C, nullptr, nullptr, M, N, K);
}
static void run_gemm_bias_res(const float* A, const float* B, float* C,
                              const float* bias, const float* resid, int M, int N, int K)
{
    dim3 grid(N / 128, M / 128);
    gemm_tf32_kernel<1, true><<<grid, 256>>>(A, B, C, bias, resid, M, N, K);
}
static void run_gemm_bias_gelu(const float* A, const float* B, float* C,
                               const float* bias, int M, int N, int K)
{
    dim3 grid(N / 128, M / 128);
    gemm_tf32_kernel<2, false><<<grid, 256>>>(A, B, C, bias, nullptr, M, N, K);
}

extern "C" void kernel_launch(void* const* d_in, const int* in_sizes, int n_in,
                              void* d_out, int out_size)
{
    const float* x1    = (const float*)d_in[0];
    const float* x2    = (const float*)d_in[1];
    const float* x3    = (const float*)d_in[2];
    const float* ln11g = (const float*)d_in[3];
    const float* ln11b = (const float*)d_in[4];
    const float* ln12g = (const float*)d_in[5];
    const float* ln12b = (const float*)d_in[6];
    const float* ln21g = (const float*)d_in[7];
    const float* ln21b = (const float*)d_in[8];
    const float* ln23g = (const float*)d_in[9];
    const float* ln23b = (const float*)d_in[10];
    const float* ln2g  = (const float*)d_in[11];
    const float* ln2b  = (const float*)d_in[12];
    const float* a1wq  = (const float*)d_in[13];
    const float* a1wk  = (const float*)d_in[14];
    const float* a1wv  = (const float*)d_in[15];
    const float* a1wp  = (const float*)d_in[16];
    const float* a1bp  = (const float*)d_in[17];
    const float* a2wq  = (const float*)d_in[18];
    const float* a2wk  = (const float*)d_in[19];
    const float* a2wv  = (const float*)d_in[20];
    const float* a2wp  = (const float*)d_in[21];
    const float* a2bp  = (const float*)d_in[22];
    const float* fc1w  = (const float*)d_in[23];
    const float* fc1b  = (const float*)d_in[24];
    const float* fc2w  = (const float*)d_in[25];
    const float* fc2b  = (const float*)d_in[26];
    float* out = (float*)d_out;

    float *lnq, *lnkv, *q, *k, *v, *o, *x, *hbuf;
    cudaGetSymbolAddress((void**)&lnq,  g_lnq);
    cudaGetSymbolAddress((void**)&lnkv, g_lnkv);
    cudaGetSymbolAddress((void**)&q,    g_q);
    cudaGetSymbolAddress((void**)&k,    g_k);
    cudaGetSymbolAddress((void**)&v,    g_v);
    cudaGetSymbolAddress((void**)&o,    g_o);
    cudaGetSymbolAddress((void**)&x,    g_x);
    cudaGetSymbolAddress((void**)&hbuf, g_h);

    cudaFuncSetAttribute(attn_kernel, cudaFuncAttributeMaxDynamicSharedMemorySize,
                         (int)ATT_SMEM);

    const dim3 attn_grid(SEQ / 64, NHEAD, BATCH);

    // ---- branch 1: cross-attn(LN(x1), LN(x2)) ----
    ln_kernel<<<ROWS, 256>>>(x1, ln11g, ln11b, lnq);
    ln_kernel<<<ROWS, 256>>>(x2, ln12g, ln12b, lnkv);
    run_gemm_plain(lnq,  a1wq, q, ROWS, CH, CH);
    run_gemm_plain(lnkv, a1wk, k, ROWS, CH, CH);
    run_gemm_plain(lnkv, a1wv, v, ROWS, CH, CH);
    attn_kernel<<<attn_grid, 256, ATT_SMEM>>>(q, k, v, o);
    run_gemm_bias_res(o, a1wp, x, a1bp, x1, ROWS, CH, CH);   // x = x1 + br1

    // ---- branch 2: cross-attn(LN(x1), LN(x3)) ----
    ln_kernel<<<ROWS, 256>>>(x1, ln21g, ln21b, lnq);
    ln_kernel<<<ROWS, 256>>>(x3, ln23g, ln23b, lnkv);
    run_gemm_plain(lnq,  a2wq, q, ROWS, CH, CH);
    run_gemm_plain(lnkv, a2wk, k, ROWS, CH, CH);
    run_gemm_plain(lnkv, a2wv, v, ROWS, CH, CH);
    attn_kernel<<<attn_grid, 256, ATT_SMEM>>>(q, k, v, o);
    run_gemm_bias_res(o, a2wp, x, a2bp, x, ROWS, CH, CH);    // x += br2 (in-place resid)

    // ---- MLP ----
    ln_kernel<<<ROWS, 256>>>(x, ln2g, ln2b, lnq);
    run_gemm_bias_gelu(lnq, fc1w, hbuf, fc1b, ROWS, HID, CH);   // h = gelu(y@fc1+b1)
    run_gemm_bias_res(hbuf, fc2w, out, fc2b, x, ROWS, CH, HID); // out = x + h@fc2+b2
}

// round 8
// speedup vs baseline: 4.4033x; 3.2179x over previous
#include <cuda_runtime.h>
#include <math.h>

// ---------------------------------------------------------------------------
// Shapes (fixed by the problem)
// ---------------------------------------------------------------------------
#define BATCH 8
#define SEQ   1024
#define CH    1024
#define HID   4096
#define NHEAD 16
#define HDIM  64          // CH / NHEAD
#define ROWS  (BATCH*SEQ) // 8192

// ---------------------------------------------------------------------------
// Scratch (device globals: no runtime allocation allowed)
// ---------------------------------------------------------------------------
__device__ float g_lnq [ROWS*CH];
__device__ float g_lnkv[ROWS*CH];
__device__ float g_q   [ROWS*CH];
__device__ float g_k   [ROWS*CH];
__device__ float g_v   [ROWS*CH];
__device__ float g_o   [ROWS*CH];
__device__ float g_x   [ROWS*CH];
__device__ float g_h   [ROWS*HID];

// ---------------------------------------------------------------------------
// Common tf32 helpers (fragment mapping validated in round 6)
// ---------------------------------------------------------------------------
__device__ __forceinline__ unsigned f2tf32(float f) {
    unsigned r;
    asm("cvt.rna.tf32.f32 %0, %1;" : "=r"(r) : "f"(f));
    return r;
}

__device__ __forceinline__ void mma_tf32(float* d,
                                         const unsigned* a, const unsigned* b) {
    asm("mma.sync.aligned.m16n8k8.row.col.f32.tf32.tf32.f32 "
        "{%0,%1,%2,%3}, {%4,%5,%6,%7}, {%8,%9}, {%0,%1,%2,%3};"
        : "+f"(d[0]), "+f"(d[1]), "+f"(d[2]), "+f"(d[3])
        : "r"(a[0]), "r"(a[1]), "r"(a[2]), "r"(a[3]), "r"(b[0]), "r"(b[1]));
}

// ---------------------------------------------------------------------------
// LayerNorm: one block per row, C = 1024 fixed
// ---------------------------------------------------------------------------
__global__ void __launch_bounds__(256)
ln_kernel(const float* __restrict__ x, const float* __restrict__ g,
          const float* __restrict__ b, float* __restrict__ y)
{
    const int row = blockIdx.x;
    const int t   = threadIdx.x;
    const float4 xv = reinterpret_cast<const float4*>(x + (size_t)row*CH)[t];

    float s  = xv.x + xv.y + xv.z + xv.w;
    float ss = xv.x*xv.x + xv.y*xv.y + xv.z*xv.z + xv.w*xv.w;
    #pragma unroll
    for (int o = 16; o; o >>= 1) {
        s  += __shfl_xor_sync(0xffffffffu, s,  o);
        ss += __shfl_xor_sync(0xffffffffu, ss, o);
    }
    __shared__ float sh_s[8], sh_ss[8];
    if ((t & 31) == 0) { sh_s[t >> 5] = s; sh_ss[t >> 5] = ss; }
    __syncthreads();
    float ts = 0.f, tss = 0.f;
    #pragma unroll
    for (int i = 0; i < 8; i++) { ts += sh_s[i]; tss += sh_ss[i]; }

    const float mean = ts * (1.0f / CH);
    const float var  = tss * (1.0f / CH) - mean * mean;
    const float rstd = rsqrtf(var + 1e-5f);

    const float4 gv = reinterpret_cast<const float4*>(g)[t];
    const float4 bv = reinterpret_cast<const float4*>(b)[t];
    float4 out;
    out.x = (xv.x - mean) * rstd * gv.x + bv.x;
    out.y = (xv.y - mean) * rstd * gv.y + bv.y;
    out.z = (xv.z - mean) * rstd * gv.z + bv.z;
    out.w = (xv.w - mean) * rstd * gv.w + bv.w;
    reinterpret_cast<float4*>(y + (size_t)row*CH)[t] = out;
}

// ---------------------------------------------------------------------------
// TF32 tensor-core GEMM (unchanged from round 6 — validated)
// ---------------------------------------------------------------------------
#define AS_STRIDE 18
#define BS_STRIDE 136

template<int OP, bool HASRES>
__global__ void __launch_bounds__(256, 2)
gemm_tf32_kernel(const float* __restrict__ A, const float* __restrict__ B,
                 float* __restrict__ C, const float* __restrict__ bias,
                 const float* __restrict__ resid, int M, int N, int K)
{
    __shared__ unsigned As[2][128][AS_STRIDE];
    __shared__ unsigned Bs[2][16][BS_STRIDE];

    const int t    = threadIdx.x;
    const int warp = t >> 5;
    const int lane = t & 31;
    const int g    = lane >> 2;
    const int q    = lane & 3;
    const int wm   = (warp >> 2) * 64;
    const int wn   = (warp & 3) * 32;

    const int bx = blockIdx.x;
    const int by = blockIdx.y;
    const float* Ablk = A + (size_t)(by * 128) * K;
    const float* Bblk = B + bx * 128;

    const int a_row = t >> 2;
    const int a_col = (t & 3) * 4;
    const int b_row = t >> 5;
    const int b_col = (t & 31) * 4;

    float acc[4][4][4];
    #pragma unroll
    for (int f = 0; f < 4; f++)
        #pragma unroll
        for (int j = 0; j < 4; j++)
            #pragma unroll
            for (int r = 0; r < 4; r++) acc[f][j][r] = 0.f;

    {
        float4 av0 = *reinterpret_cast<const float4*>(Ablk + (size_t)a_row * K + a_col);
        float4 av1 = *reinterpret_cast<const float4*>(Ablk + (size_t)(a_row + 64) * K + a_col);
        float4 bv0 = *reinterpret_cast<const float4*>(Bblk + (size_t)b_row * N + b_col);
        float4 bv1 = *reinterpret_cast<const float4*>(Bblk + (size_t)(b_row + 8) * N + b_col);
        unsigned* pa0 = &As[0][a_row][a_col];
        pa0[0]=f2tf32(av0.x); pa0[1]=f2tf32(av0.y); pa0[2]=f2tf32(av0.z); pa0[3]=f2tf32(av0.w);
        unsigned* pa1 = &As[0][a_row + 64][a_col];
        pa1[0]=f2tf32(av1.x); pa1[1]=f2tf32(av1.y); pa1[2]=f2tf32(av1.z); pa1[3]=f2tf32(av1.w);
        unsigned* pb0 = &Bs[0][b_row][b_col];
        pb0[0]=f2tf32(bv0.x); pb0[1]=f2tf32(bv0.y); pb0[2]=f2tf32(bv0.z); pb0[3]=f2tf32(bv0.w);
        unsigned* pb1 = &Bs[0][b_row + 8][b_col];
        pb1[0]=f2tf32(bv1.x); pb1[1]=f2tf32(bv1.y); pb1[2]=f2tf32(bv1.z); pb1[3]=f2tf32(bv1.w);
    }
    __syncthreads();

    const int ktiles = K >> 4;
    for (int kt = 0; kt < ktiles; kt++) {
        const int buf  = kt & 1;
        const bool more = (kt + 1) < ktiles;

        float4 av0, av1, bv0, bv1;
        if (more) {
            const int k0 = (kt + 1) << 4;
            av0 = *reinterpret_cast<const float4*>(Ablk + (size_t)a_row * K + k0 + a_col);
            av1 = *reinterpret_cast<const float4*>(Ablk + (size_t)(a_row + 64) * K + k0 + a_col);
            bv0 = *reinterpret_cast<const float4*>(Bblk + (size_t)(k0 + b_row) * N + b_col);
            bv1 = *reinterpret_cast<const float4*>(Bblk + (size_t)(k0 + 8 + b_row) * N + b_col);
        }

        #pragma unroll
        for (int s = 0; s < 2; s++) {
            const int k8 = s * 8;
            unsigned af[4][4];
            #pragma unroll
            for (int f = 0; f < 4; f++) {
                const int m0 = wm + f * 16;
                af[f][0] = As[buf][m0 + g    ][k8 + q];
                af[f][1] = As[buf][m0 + g + 8][k8 + q];
                af[f][2] = As[buf][m0 + g    ][k8 + q + 4];
                af[f][3] = As[buf][m0 + g + 8][k8 + q + 4];
            }
            unsigned bf[4][2];
            #pragma unroll
            for (int j = 0; j < 4; j++) {
                const int n0 = wn + j * 8 + g;
                bf[j][0] = Bs[buf][k8 + q    ][n0];
                bf[j][1] = Bs[buf][k8 + q + 4][n0];
            }
            #pragma unroll
            for (int f = 0; f < 4; f++)
                #pragma unroll
                for (int j = 0; j < 4; j++)
                    mma_tf32(acc[f][j], af[f], bf[j]);
        }

        if (more) {
            const int nbuf = buf ^ 1;
            unsigned* pa0 = &As[nbuf][a_row][a_col];
            pa0[0]=f2tf32(av0.x); pa0[1]=f2tf32(av0.y); pa0[2]=f2tf32(av0.z); pa0[3]=f2tf32(av0.w);
            unsigned* pa1 = &As[nbuf][a_row + 64][a_col];
            pa1[0]=f2tf32(av1.x); pa1[1]=f2tf32(av1.y); pa1[2]=f2tf32(av1.z); pa1[3]=f2tf32(av1.w);
            unsigned* pb0 = &Bs[nbuf][b_row][b_col];
            pb0[0]=f2tf32(bv0.x); pb0[1]=f2tf32(bv0.y); pb0[2]=f2tf32(bv0.z); pb0[3]=f2tf32(bv0.w);
            unsigned* pb1 = &Bs[nbuf][b_row + 8][b_col];
            pb1[0]=f2tf32(bv1.x); pb1[1]=f2tf32(bv1.y); pb1[2]=f2tf32(bv1.z); pb1[3]=f2tf32(bv1.w);
        }
        __syncthreads();
    }

    #pragma unroll
    for (int f = 0; f < 4; f++) {
        const int r0 = by * 128 + wm + f * 16 + g;
        #pragma unroll
        for (int j = 0; j < 4; j++) {
            const int c0 = bx * 128 + wn + j * 8 + 2 * q;
            float v00 = acc[f][j][0], v01 = acc[f][j][1];
            float v10 = acc[f][j][2], v11 = acc[f][j][3];
            if (OP >= 1) {
                const float b0 = bias[c0], b1 = bias[c0 + 1];
                v00 += b0; v01 += b1; v10 += b0; v11 += b1;
            }
            if (OP == 2) {
                v00 = 0.5f * v00 * (1.0f + erff(v00 * 0.70710678118654752f));
                v01 = 0.5f * v01 * (1.0f + erff(v01 * 0.70710678118654752f));
                v10 = 0.5f * v10 * (1.0f + erff(v10 * 0.70710678118654752f));
                v11 = 0.5f * v11 * (1.0f + erff(v11 * 0.70710678118654752f));
            }
            const size_t off0 = (size_t)r0 * N + c0;
            const size_t off1 = (size_t)(r0 + 8) * N + c0;
            if (HASRES) {
                const float2 rr0 = *reinterpret_cast<const float2*>(resid + off0);
                const float2 rr1 = *reinterpret_cast<const float2*>(resid + off1);
                v00 += rr0.x; v01 += rr0.y; v10 += rr1.x; v11 += rr1.y;
            }
            float2 w0; w0.x = v00; w0.y = v01;
            float2 w1; w1.x = v10; w1.y = v11;
            *reinterpret_cast<float2*>(C + off0) = w0;
            *reinterpret_cast<float2*>(C + off1) = w1;
        }
    }
}

// ---------------------------------------------------------------------------
// TF32 tensor-core flash attention.
// Block: 64 queries x one (b,h). 128 threads = 4 warps; warp w owns query
// rows [w*16, w*16+16) and the FULL key/d range -> softmax is warp-local.
// Per 64-key tile: S = Q K^T (64 mma/warp), online softmax in registers,
// P -> smem (same-warp rows, __syncwarp only), O += P V (64 mma/warp).
// Ks stored transposed [d][key] with XOR swizzle col^=(d>>2)*2
// (conflict-free transpose stores AND fragment reads). A-tiles stride 68,
// B-tiles stride 72 (both conflict-free for their fragment patterns).
// ---------------------------------------------------------------------------
#define AQ_STRIDE 68   // A-operand tiles (Q, P): 64 + 4
#define BK_STRIDE 72   // B-operand tiles (K^T, V): 64 + 8
#define ATT2_SMEM ((2 * 64 * AQ_STRIDE + 2 * 64 * BK_STRIDE) * sizeof(unsigned))

__global__ void __launch_bounds__(128)
attn_tf32_kernel(const float* __restrict__ Q, const float* __restrict__ K,
                 const float* __restrict__ V, float* __restrict__ O)
{
    extern __shared__ unsigned smbase[];
    unsigned (*Qs)[AQ_STRIDE] = reinterpret_cast<unsigned(*)[AQ_STRIDE]>(smbase);
    unsigned (*Ps)[AQ_STRIDE] = reinterpret_cast<unsigned(*)[AQ_STRIDE]>(smbase + 64 * AQ_STRIDE);
    unsigned (*Ks)[BK_STRIDE] = reinterpret_cast<unsigned(*)[BK_STRIDE]>(smbase + 2 * 64 * AQ_STRIDE);
    unsigned (*Vs)[BK_STRIDE] = reinterpret_cast<unsigned(*)[BK_STRIDE]>(smbase + 2 * 64 * AQ_STRIDE + 64 * BK_STRIDE);

    const int q0   = blockIdx.x * 64;
    const int h    = blockIdx.y;
    const int b    = blockIdx.z;
    const int tid  = threadIdx.x;
    const int warp = tid >> 5;
    const int lane = tid & 31;
    const int g    = lane >> 2;
    const int q    = lane & 3;
    const int wm   = warp * 16;

    // ---- load Q tile (64x64), tf32 in smem ----
    #pragma unroll
    for (int i = 0; i < 8; i++) {
        const int idx = tid + i * 128;            // 0..1023
        const int row = idx >> 4;
        const int c4  = (idx & 15) * 4;
        const float4 v4 = *reinterpret_cast<const float4*>(
            Q + ((size_t)(b * SEQ + q0 + row)) * CH + h * HDIM + c4);
        unsigned* p = &Qs[row][c4];
        p[0] = f2tf32(v4.x); p[1] = f2tf32(v4.y);
        p[2] = f2tf32(v4.z); p[3] = f2tf32(v4.w);
    }

    float m0 = -1e30f, m1 = -1e30f, l0 = 0.f, l1 = 0.f;
    float oacc[8][4];
    #pragma unroll
    for (int j = 0; j < 8; j++)
        #pragma unroll
        for (int r = 0; r < 4; r++) oacc[j][r] = 0.f;

    for (int t0 = 0; t0 < SEQ; t0 += 64) {
        __syncthreads();   // protect Ks/Vs reuse (covers Qs on iter 0 too)

        // ---- load K (transposed+swizzled) and V (natural) tiles ----
        #pragma unroll
        for (int i = 0; i < 8; i++) {
            const int idx = tid + i * 128;
            const int row = idx >> 4;             // key index
            const int c4  = (idx & 15) * 4;       // d base
            const size_t goff = ((size_t)(b * SEQ + t0 + row)) * CH + h * HDIM + c4;
            const float4 kv = *reinterpret_cast<const float4*>(K + goff);
            const float4 vv = *reinterpret_cast<const float4*>(V + goff);
            const int swz = (c4 >> 2) * 2;        // same for d = c4..c4+3
            const int colk = row ^ swz;
            Ks[c4 + 0][colk] = f2tf32(kv.x);
            Ks[c4 + 1][colk] = f2tf32(kv.y);
            Ks[c4 + 2][colk] = f2tf32(kv.z);
            Ks[c4 + 3][colk] = f2tf32(kv.w);
            unsigned* pv = &Vs[row][c4];
            pv[0] = f2tf32(vv.x); pv[1] = f2tf32(vv.y);
            pv[2] = f2tf32(vv.z); pv[3] = f2tf32(vv.w);
        }
        __syncthreads();

        // ---- S = Q K^T (warp rows wm..wm+15, all 64 keys) ----
        float sacc[8][4];
        #pragma unroll
        for (int j = 0; j < 8; j++)
            #pragma unroll
            for (int r = 0; r < 4; r++) sacc[j][r] = 0.f;

        #pragma unroll
        for (int ks = 0; ks < 8; ks++) {
            const int k8 = ks * 8;
            unsigned a[4];
            a[0] = Qs[wm + g    ][k8 + q];
            a[1] = Qs[wm + g + 8][k8 + q];
            a[2] = Qs[wm + g    ][k8 + q + 4];
            a[3] = Qs[wm + g + 8][k8 + q + 4];
            const int s0 = 4 * ks;       // swizzle for d-row k8+q
            const int s1 = 4 * ks + 2;   // swizzle for d-row k8+q+4
            #pragma unroll
            for (int j = 0; j < 8; j++) {
                unsigned bb[2];
                bb[0] = Ks[k8 + q    ][(j * 8 + g) ^ s0];
                bb[1] = Ks[k8 + q + 4][(j * 8 + g) ^ s1];
                mma_tf32(sacc[j], a, bb);
            }
        }

        // ---- online softmax (warp-local; rows g and g+8) ----
        float mx0 = -1e30f, mx1 = -1e30f;
        #pragma unroll
        for (int j = 0; j < 8; j++) {
            mx0 = fmaxf(mx0, fmaxf(sacc[j][0], sacc[j][1]));
            mx1 = fmaxf(mx1, fmaxf(sacc[j][2], sacc[j][3]));
        }
        mx0 = fmaxf(mx0, __shfl_xor_sync(0xffffffffu, mx0, 1));
        mx0 = fmaxf(mx0, __shfl_xor_sync(0xffffffffu, mx0, 2));
        mx1 = fmaxf(mx1, __shfl_xor_sync(0xffffffffu, mx1, 1));
        mx1 = fmaxf(mx1, __shfl_xor_sync(0xffffffffu, mx1, 2));

        const float mnew0 = fmaxf(m0, mx0 * 0.125f);
        const float mnew1 = fmaxf(m1, mx1 * 0.125f);
        const float alpha0 = __expf(m0 - mnew0);
        const float alpha1 = __expf(m1 - mnew1);
        l0 *= alpha0;
        l1 *= alpha1;

        #pragma unroll
        for (int j = 0; j < 8; j++) {
            const int c0 = j * 8 + 2 * q;
            const float p00 = __expf(sacc[j][0] * 0.125f - mnew0);
            const float p01 = __expf(sacc[j][1] * 0.125f - mnew0);
            const float p10 = __expf(sacc[j][2] * 0.125f - mnew1);
            const float p11 = __expf(sacc[j][3] * 0.125f - mnew1);
            l0 += p00 + p01;
            l1 += p10 + p11;
            Ps[wm + g    ][c0    ] = f2tf32(p00);
            Ps[wm + g    ][c0 + 1] = f2tf32(p01);
            Ps[wm + g + 8][c0    ] = f2tf32(p10);
            Ps[wm + g + 8][c0 + 1] = f2tf32(p11);
            oacc[j][0] *= alpha0; oacc[j][1] *= alpha0;
            oacc[j][2] *= alpha1; oacc[j][3] *= alpha1;
        }
        m0 = mnew0; m1 = mnew1;
        __syncwarp();   // P rows are warp-private; warp-level visibility suffices

        // ---- O += P V ----
        #pragma unroll
        for (int ks = 0; ks < 8; ks++) {
            const int k8 = ks * 8;
            unsigned a[4];
            a[0] = Ps[wm + g    ][k8 + q];
            a[1] = Ps[wm + g + 8][k8 + q];
            a[2] = Ps[wm + g    ][k8 + q + 4];
            a[3] = Ps[wm + g + 8][k8 + q + 4];
            #pragma unroll
            for (int j = 0; j < 8; j++) {
                unsigned bb[2];
                bb[0] = Vs[k8 + q    ][j * 8 + g];
                bb[1] = Vs[k8 + q + 4][j * 8 + g];
                mma_tf32(oacc[j], a, bb);
            }
        }
        __syncwarp();   // P reads complete before next-iter overwrite
    }

    // ---- finalize: row sums across quad, normalize, store ----
    l0 += __shfl_xor_sync(0xffffffffu, l0, 1);
    l0 += __shfl_xor_sync(0xffffffffu, l0, 2);
    l1 += __shfl_xor_sync(0xffffffffu, l1, 1);
    l1 += __shfl_xor_sync(0xffffffffu, l1, 2);
    const float inv0 = 1.0f / l0;
    const float inv1 = 1.0f / l1;

    const size_t row0 = (size_t)(b * SEQ + q0 + wm + g);
    #pragma unroll
    for (int j = 0; j < 8; j++) {
        const int c0 = h * HDIM + j * 8 + 2 * q;
        float2 w0; w0.x = oacc[j][0] * inv0; w0.y = oacc[j][1] * inv0;
        float2 w1; w1.x = oacc[j][2] * inv1; w1.y = oacc[j][3] * inv1;
        *reinterpret_cast<float2*>(O + row0 * CH + c0)       = w0;
        *reinterpret_cast<float2*>(O + (row0 + 8) * CH + c0) = w1;
    }
}

// ---------------------------------------------------------------------------
// Host-side orchestration
// ---------------------------------------------------------------------------
static void run_gemm_plain(const float* A, const float* B, float* C, int M, int N, int K)
{
    dim3 grid(N / 128, M / 128);
    gemm_tf32_kernel<0, false><<<grid, 256>>>(A, B, C, nullptr, nullptr, M, N, K);
}
static void run_gemm_bias_res(const float* A, const float* B, float* C,
                              const float* bias, const float* resid, int M, int N, int K)
{
    dim3 grid(N / 128, M / 128);
    gemm_tf32_kernel<1, true><<<grid, 256>>>(A, B, C, bias, resid, M, N, K);
}
static void run_gemm_bias_gelu(const float* A, const float* B, float* C,
                               const float* bias, int M, int N, int K)
{
    dim3 grid(N / 128, M / 128);
    gemm_tf32_kernel<2, false><<<grid, 256>>>(A, B, C, bias, nullptr, M, N, K);
}

extern "C" void kernel_launch(void* const* d_in, const int* in_sizes, int n_in,
                              void* d_out, int out_size)
{
    const float* x1    = (const float*)d_in[0];
    const float* x2    = (const float*)d_in[1];
    const float* x3    = (const float*)d_in[2];
    const float* ln11g = (const float*)d_in[3];
    const float* ln11b = (const float*)d_in[4];
    const float* ln12g = (const float*)d_in[5];
    const float* ln12b = (const float*)d_in[6];
    const float* ln21g = (const float*)d_in[7];
    const float* ln21b = (const float*)d_in[8];
    const float* ln23g = (const float*)d_in[9];
    const float* ln23b = (const float*)d_in[10];
    const float* ln2g  = (const float*)d_in[11];
    const float* ln2b  = (const float*)d_in[12];
    const float* a1wq  = (const float*)d_in[13];
    const float* a1wk  = (const float*)d_in[14];
    const float* a1wv  = (const float*)d_in[15];
    const float* a1wp  = (const float*)d_in[16];
    const float* a1bp  = (const float*)d_in[17];
    const float* a2wq  = (const float*)d_in[18];
    const float* a2wk  = (const float*)d_in[19];
    const float* a2wv  = (const float*)d_in[20];
    const float* a2wp  = (const float*)d_in[21];
    const float* a2bp  = (const float*)d_in[22];
    const float* fc1w  = (const float*)d_in[23];
    const float* fc1b  = (const float*)d_in[24];
    const float* fc2w  = (const float*)d_in[25];
    const float* fc2b  = (const float*)d_in[26];
    float* out = (float*)d_out;

    float *lnq, *lnkv, *q, *k, *v, *o, *x, *hbuf;
    cudaGetSymbolAddress((void**)&lnq,  g_lnq);
    cudaGetSymbolAddress((void**)&lnkv, g_lnkv);
    cudaGetSymbolAddress((void**)&q,    g_q);
    cudaGetSymbolAddress((void**)&k,    g_k);
    cudaGetSymbolAddress((void**)&v,    g_v);
    cudaGetSymbolAddress((void**)&o,    g_o);
    cudaGetSymbolAddress((void**)&x,    g_x);
    cudaGetSymbolAddress((void**)&hbuf, g_h);

    cudaFuncSetAttribute(attn_tf32_kernel, cudaFuncAttributeMaxDynamicSharedMemorySize,
                         (int)ATT2_SMEM);

    const dim3 attn_grid(SEQ / 64, NHEAD, BATCH);

    // ---- branch 1: cross-attn(LN(x1), LN(x2)) ----
    ln_kernel<<<ROWS, 256>>>(x1, ln11g, ln11b, lnq);
    ln_kernel<<<ROWS, 256>>>(x2, ln12g, ln12b, lnkv);
    run_gemm_plain(lnq,  a1wq, q, ROWS, CH, CH);
    run_gemm_plain(lnkv, a1wk, k, ROWS, CH, CH);
    run_gemm_plain(lnkv, a1wv, v, ROWS, CH, CH);
    attn_tf32_kernel<<<attn_grid, 128, ATT2_SMEM>>>(q, k, v, o);
    run_gemm_bias_res(o, a1wp, x, a1bp, x1, ROWS, CH, CH);   // x = x1 + br1

    // ---- branch 2: cross-attn(LN(x1), LN(x3)) ----
    ln_kernel<<<ROWS, 256>>>(x1, ln21g, ln21b, lnq);
    ln_kernel<<<ROWS, 256>>>(x3, ln23g, ln23b, lnkv);
    run_gemm_plain(lnq,  a2wq, q, ROWS, CH, CH);
    run_gemm_plain(lnkv, a2wk, k, ROWS, CH, CH);
    run_gemm_plain(lnkv, a2wv, v, ROWS, CH, CH);
    attn_tf32_kernel<<<attn_grid, 128, ATT2_SMEM>>>(q, k, v, o);
    run_gemm_bias_res(o, a2wp, x, a2bp, x, ROWS, CH, CH);    // x += br2 (in-place resid)

    // ---- MLP ----
    ln_kernel<<<ROWS, 256>>>(x, ln2g, ln2b, lnq);
    run_gemm_bias_gelu(lnq, fc1w, hbuf, fc1b, ROWS, HID, CH);   // h = gelu(y@fc1+b1)
    run_gemm_bias_res(hbuf, fc2w, out, fc2b, x, ROWS, CH, HID); // out = x + h@fc2+b2
}

// round 10
// speedup vs baseline: 4.8373x; 1.0986x over previous
#include <cuda_runtime.h>
#include <math.h>

// ---------------------------------------------------------------------------
// Shapes (fixed by the problem)
// ---------------------------------------------------------------------------
#define BATCH 8
#define SEQ   1024
#define CH    1024
#define HID   4096
#define NHEAD 16
#define HDIM  64          // CH / NHEAD
#define ROWS  (BATCH*SEQ) // 8192

// ---------------------------------------------------------------------------
// Scratch (device globals: no runtime allocation allowed)
// ---------------------------------------------------------------------------
__device__ float g_lnq [ROWS*CH];
__device__ float g_lnkv[ROWS*CH];
__device__ float g_q   [ROWS*CH];
__device__ float g_k   [ROWS*CH];
__device__ float g_v   [ROWS*CH];
__device__ float g_o   [ROWS*CH];
__device__ float g_x   [ROWS*CH];
__device__ float g_h   [ROWS*HID];   // MLP hidden; front 32MB doubles as LN21(x1) buffer

// ---------------------------------------------------------------------------
// Common tf32 helpers (fragment mapping validated in rounds 6/8)
// ---------------------------------------------------------------------------
__device__ __forceinline__ unsigned f2tf32(float f) {
    unsigned r;
    asm("cvt.rna.tf32.f32 %0, %1;" : "=r"(r) : "f"(f));
    return r;
}

__device__ __forceinline__ void mma_tf32(float* d,
                                         const unsigned* a, const unsigned* b) {
    asm("mma.sync.aligned.m16n8k8.row.col.f32.tf32.tf32.f32 "
        "{%0,%1,%2,%3}, {%4,%5,%6,%7}, {%8,%9}, {%0,%1,%2,%3};"
        : "+f"(d[0]), "+f"(d[1]), "+f"(d[2]), "+f"(d[3])
        : "r"(a[0]), "r"(a[1]), "r"(a[2]), "r"(a[3]), "r"(b[0]), "r"(b[1]));
}

// ---------------------------------------------------------------------------
// LayerNorm: one block per row, C = 1024 fixed
// ---------------------------------------------------------------------------
__global__ void __launch_bounds__(256)
ln_kernel(const float* __restrict__ x, const float* __restrict__ g,
          const float* __restrict__ b, float* __restrict__ y)
{
    const int row = blockIdx.x;
    const int t   = threadIdx.x;
    const float4 xv = reinterpret_cast<const float4*>(x + (size_t)row*CH)[t];

    float s  = xv.x + xv.y + xv.z + xv.w;
    float ss = xv.x*xv.x + xv.y*xv.y + xv.z*xv.z + xv.w*xv.w;
    #pragma unroll
    for (int o = 16; o; o >>= 1) {
        s  += __shfl_xor_sync(0xffffffffu, s,  o);
        ss += __shfl_xor_sync(0xffffffffu, ss, o);
    }
    __shared__ float sh_s[8], sh_ss[8];
    if ((t & 31) == 0) { sh_s[t >> 5] = s; sh_ss[t >> 5] = ss; }
    __syncthreads();
    float ts = 0.f, tss = 0.f;
    #pragma unroll
    for (int i = 0; i < 8; i++) { ts += sh_s[i]; tss += sh_ss[i]; }

    const float mean = ts * (1.0f / CH);
    const float var  = tss * (1.0f / CH) - mean * mean;
    const float rstd = rsqrtf(var + 1e-5f);

    const float4 gv = reinterpret_cast<const float4*>(g)[t];
    const float4 bv = reinterpret_cast<const float4*>(b)[t];
    float4 out;
    out.x = (xv.x - mean) * rstd * gv.x + bv.x;
    out.y = (xv.y - mean) * rstd * gv.y + bv.y;
    out.z = (xv.z - mean) * rstd * gv.z + bv.z;
    out.w = (xv.w - mean) * rstd * gv.w + bv.w;
    reinterpret_cast<float4*>(y + (size_t)row*CH)[t] = out;
}

// Dual-affine LN: one reduction over x, two (gamma,beta) outputs.
__global__ void __launch_bounds__(256)
ln_dual_kernel(const float* __restrict__ x,
               const float* __restrict__ g1, const float* __restrict__ b1, float* __restrict__ y1,
               const float* __restrict__ g2, const float* __restrict__ b2, float* __restrict__ y2)
{
    const int row = blockIdx.x;
    const int t   = threadIdx.x;
    const float4 xv = reinterpret_cast<const float4*>(x + (size_t)row*CH)[t];

    float s  = xv.x + xv.y + xv.z + xv.w;
    float ss = xv.x*xv.x + xv.y*xv.y + xv.z*xv.z + xv.w*xv.w;
    #pragma unroll
    for (int o = 16; o; o >>= 1) {
        s  += __shfl_xor_sync(0xffffffffu, s,  o);
        ss += __shfl_xor_sync(0xffffffffu, ss, o);
    }
    __shared__ float sh_s[8], sh_ss[8];
    if ((t & 31) == 0) { sh_s[t >> 5] = s; sh_ss[t >> 5] = ss; }
    __syncthreads();
    float ts = 0.f, tss = 0.f;
    #pragma unroll
    for (int i = 0; i < 8; i++) { ts += sh_s[i]; tss += sh_ss[i]; }

    const float mean = ts * (1.0f / CH);
    const float var  = tss * (1.0f / CH) - mean * mean;
    const float rstd = rsqrtf(var + 1e-5f);

    const float nx0 = (xv.x - mean) * rstd;
    const float nx1 = (xv.y - mean) * rstd;
    const float nx2 = (xv.z - mean) * rstd;
    const float nx3 = (xv.w - mean) * rstd;

    {
        const float4 gv = reinterpret_cast<const float4*>(g1)[t];
        const float4 bv = reinterpret_cast<const float4*>(b1)[t];
        float4 o1;
        o1.x = nx0 * gv.x + bv.x; o1.y = nx1 * gv.y + bv.y;
        o1.z = nx2 * gv.z + bv.z; o1.w = nx3 * gv.w + bv.w;
        reinterpret_cast<float4*>(y1 + (size_t)row*CH)[t] = o1;
    }
    {
        const float4 gv = reinterpret_cast<const float4*>(g2)[t];
        const float4 bv = reinterpret_cast<const float4*>(b2)[t];
        float4 o2;
        o2.x = nx0 * gv.x + bv.x; o2.y = nx1 * gv.y + bv.y;
        o2.z = nx2 * gv.z + bv.z; o2.w = nx3 * gv.w + bv.w;
        reinterpret_cast<float4*>(y2 + (size_t)row*CH)[t] = o2;
    }
}

// ---------------------------------------------------------------------------
// TF32 tensor-core GEMM with cp.async 4-stage pipeline.
// C[M,N] = A[M,K] @ B[K,N] (+bias)(+gelu)(+resid), row-major.
// 128x128 CTA tile, BK=16, 256 threads (8 warps, 2x4), warp 64x32 via 4x4
// m16n8k8. Operands are raw fp32 bits (HW truncates to tf32).
// A stride 20, B stride 136: 16B-aligned rows for cp.async AND conflict-free
// fragment loads (banks 20g+q and 8q+g both cover all 32).
// OP: 0 = none, 1 = +bias, 2 = +bias then exact GELU
// ---------------------------------------------------------------------------
#define GS_STAGES   4
#define GA_STRIDE   20                     // words per A row
#define GB_STRIDE   136                    // words per B row
#define GA_WORDS    (128 * GA_STRIDE)      // per stage
#define GB_WORDS    (16 * GB_STRIDE)       // per stage
#define GB_BASE     (GS_STAGES * GA_WORDS) // B region start (word index)
#define GS_SMEM     ((GS_STAGES * (GA_WORDS + GB_WORDS)) * sizeof(unsigned))

template<int OP, bool HASRES>
__global__ void __launch_bounds__(256, 2)
gemm_tf32_kernel(const float* __restrict__ A, const float* __restrict__ B,
                 float* __restrict__ C, const float* __restrict__ bias,
                 const float* __restrict__ resid, int M, int N, int K)
{
    extern __shared__ unsigned sm[];
    const unsigned smem_base = (unsigned)__cvta_generic_to_shared(sm);

    const int t    = threadIdx.x;
    const int warp = t >> 5;
    const int lane = t & 31;
    const int g    = lane >> 2;
    const int q    = lane & 3;
    const int wm   = (warp >> 2) * 64;
    const int wn   = (warp & 3) * 32;

    const int bx = blockIdx.x;
    const int by = blockIdx.y;
    const float* Ablk = A + (size_t)(by * 128) * K;
    const float* Bblk = B + bx * 128;

    // per-thread cp.async chunk coords (2 A-chunks + 2 B-chunks per stage)
    const int a_row0 = t >> 1,          a_c4 = (t & 1) * 8;
    const int b_row0 = t >> 4,          b_c4 = (t & 15) * 8;

    float acc[4][4][4];
    #pragma unroll
    for (int f = 0; f < 4; f++)
        #pragma unroll
        for (int j = 0; j < 4; j++)
            #pragma unroll
            for (int r = 0; r < 4; r++) acc[f][j][r] = 0.f;

    // issue one stage's cp.asyncs (A: 128x16 fp32, B: 16x128 fp32)
    auto issue_stage = [&](int slot, int kbase) {
        {
            const float* src = Ablk + (size_t)a_row0 * K + kbase + a_c4;
            unsigned dst = smem_base + 4u * (slot * GA_WORDS + a_row0 * GA_STRIDE + a_c4);
            asm volatile("cp.async.cg.shared.global [%0], [%1], 16;" :: "r"(dst), "l"(src));
            asm volatile("cp.async.cg.shared.global [%0], [%1], 16;" :: "r"(dst + 16), "l"(src + 4));
        }
        {
            const float* src = Bblk + (size_t)(kbase + b_row0) * N + b_c4;
            unsigned dst = smem_base + 4u * (GB_BASE + slot * GB_WORDS + b_row0 * GB_STRIDE + b_c4);
            asm volatile("cp.async.cg.shared.global [%0], [%1], 16;" :: "r"(dst), "l"(src));
            asm volatile("cp.async.cg.shared.global [%0], [%1], 16;" :: "r"(dst + 16), "l"(src + 4));
        }
    };

    const int ktiles = K >> 4;

    // prologue: fill stages 0..2
    #pragma unroll
    for (int s = 0; s < GS_STAGES - 1; s++) {
        issue_stage(s, s * 16);
        asm volatile("cp.async.commit_group;");
    }

    for (int kt = 0; kt < ktiles; kt++) {
        asm volatile("cp.async.wait_group 2;");
        __syncthreads();

        const int nk = kt + GS_STAGES - 1;
        if (nk < ktiles) issue_stage(nk & (GS_STAGES - 1), nk * 16);
        asm volatile("cp.async.commit_group;");

        const int slot = kt & (GS_STAGES - 1);
        const unsigned* As = sm + slot * GA_WORDS;
        const unsigned* Bs = sm + GB_BASE + slot * GB_WORDS;

        #pragma unroll
        for (int s = 0; s < 2; s++) {
            const int k8 = s * 8;
            unsigned af[4][4];
            #pragma unroll
            for (int f = 0; f < 4; f++) {
                const int m0 = wm + f * 16;
                af[f][0] = As[(m0 + g    ) * GA_STRIDE + k8 + q];
                af[f][1] = As[(m0 + g + 8) * GA_STRIDE + k8 + q];
                af[f][2] = As[(m0 + g    ) * GA_STRIDE + k8 + q + 4];
                af[f][3] = As[(m0 + g + 8) * GA_STRIDE + k8 + q + 4];
            }
            unsigned bf[4][2];
            #pragma unroll
            for (int j = 0; j < 4; j++) {
                const int n0 = wn + j * 8 + g;
                bf[j][0] = Bs[(k8 + q    ) * GB_STRIDE + n0];
                bf[j][1] = Bs[(k8 + q + 4) * GB_STRIDE + n0];
            }
            #pragma unroll
            for (int f = 0; f < 4; f++)
                #pragma unroll
                for (int j = 0; j < 4; j++)
                    mma_tf32(acc[f][j], af[f], bf[j]);
        }
    }

    // ---- epilogue ----
    #pragma unroll
    for (int f = 0; f < 4; f++) {
        const int r0 = by * 128 + wm + f * 16 + g;
        #pragma unroll
        for (int j = 0; j < 4; j++) {
            const int c0 = bx * 128 + wn + j * 8 + 2 * q;
            float v00 = acc[f][j][0], v01 = acc[f][j][1];
            float v10 = acc[f][j][2], v11 = acc[f][j][3];
            if (OP >= 1) {
                const float b0 = bias[c0], b1 = bias[c0 + 1];
                v00 += b0; v01 += b1; v10 += b0; v11 += b1;
            }
            if (OP == 2) {
                v00 = 0.5f * v00 * (1.0f + erff(v00 * 0.70710678118654752f));
                v01 = 0.5f * v01 * (1.0f + erff(v01 * 0.70710678118654752f));
                v10 = 0.5f * v10 * (1.0f + erff(v10 * 0.70710678118654752f));
                v11 = 0.5f * v11 * (1.0f + erff(v11 * 0.70710678118654752f));
            }
            const size_t off0 = (size_t)r0 * N + c0;
            const size_t off1 = (size_t)(r0 + 8) * N + c0;
            if (HASRES) {
                const float2 rr0 = *reinterpret_cast<const float2*>(resid + off0);
                const float2 rr1 = *reinterpret_cast<const float2*>(resid + off1);
                v00 += rr0.x; v01 += rr0.y; v10 += rr1.x; v11 += rr1.y;
            }
            float2 w0; w0.x = v00; w0.y = v01;
            float2 w1; w1.x = v10; w1.y = v11;
            *reinterpret_cast<float2*>(C + off0) = w0;
            *reinterpret_cast<float2*>(C + off1) = w1;
        }
    }
}

// ---------------------------------------------------------------------------
// TF32 tensor-core flash attention (unchanged — validated in round 8)
// ---------------------------------------------------------------------------
#define AQ_STRIDE 68
#define BK_STRIDE 72
#define ATT2_SMEM ((2 * 64 * AQ_STRIDE + 2 * 64 * BK_STRIDE) * sizeof(unsigned))

__global__ void __launch_bounds__(128)
attn_tf32_kernel(const float* __restrict__ Q, const float* __restrict__ K,
                 const float* __restrict__ V, float* __restrict__ O)
{
    extern __shared__ unsigned smbase[];
    unsigned (*Qs)[AQ_STRIDE] = reinterpret_cast<unsigned(*)[AQ_STRIDE]>(smbase);
    unsigned (*Ps)[AQ_STRIDE] = reinterpret_cast<unsigned(*)[AQ_STRIDE]>(smbase + 64 * AQ_STRIDE);
    unsigned (*Ks)[BK_STRIDE] = reinterpret_cast<unsigned(*)[BK_STRIDE]>(smbase + 2 * 64 * AQ_STRIDE);
    unsigned (*Vs)[BK_STRIDE] = reinterpret_cast<unsigned(*)[BK_STRIDE]>(smbase + 2 * 64 * AQ_STRIDE + 64 * BK_STRIDE);

    const int q0   = blockIdx.x * 64;
    const int h    = blockIdx.y;
    const int b    = blockIdx.z;
    const int tid  = threadIdx.x;
    const int warp = tid >> 5;
    const int lane = tid & 31;
    const int g    = lane >> 2;
    const int q    = lane & 3;
    const int wm   = warp * 16;

    #pragma unroll
    for (int i = 0; i < 8; i++) {
        const int idx = tid + i * 128;
        const int row = idx >> 4;
        const int c4  = (idx & 15) * 4;
        const float4 v4 = *reinterpret_cast<const float4*>(
            Q + ((size_t)(b * SEQ + q0 + row)) * CH + h * HDIM + c4);
        unsigned* p = &Qs[row][c4];
        p[0] = f2tf32(v4.x); p[1] = f2tf32(v4.y);
        p[2] = f2tf32(v4.z); p[3] = f2tf32(v4.w);
    }

    float m0 = -1e30f, m1 = -1e30f, l0 = 0.f, l1 = 0.f;
    float oacc[8][4];
    #pragma unroll
    for (int j = 0; j < 8; j++)
        #pragma unroll
        for (int r = 0; r < 4; r++) oacc[j][r] = 0.f;

    for (int t0 = 0; t0 < SEQ; t0 += 64) {
        __syncthreads();
        #pragma unroll
        for (int i = 0; i < 8; i++) {
            const int idx = tid + i * 128;
            const int row = idx >> 4;
            const int c4  = (idx & 15) * 4;
            const size_t goff = ((size_t)(b * SEQ + t0 + row)) * CH + h * HDIM + c4;
            const float4 kv = *reinterpret_cast<const float4*>(K + goff);
            const float4 vv = *reinterpret_cast<const float4*>(V + goff);
            const int swz = (c4 >> 2) * 2;
            const int colk = row ^ swz;
            Ks[c4 + 0][colk] = f2tf32(kv.x);
            Ks[c4 + 1][colk] = f2tf32(kv.y);
            Ks[c4 + 2][colk] = f2tf32(kv.z);
            Ks[c4 + 3][colk] = f2tf32(kv.w);
            unsigned* pv = &Vs[row][c4];
            pv[0] = f2tf32(vv.x); pv[1] = f2tf32(vv.y);
            pv[2] = f2tf32(vv.z); pv[3] = f2tf32(vv.w);
        }
        __syncthreads();

        float sacc[8][4];
        #pragma unroll
        for (int j = 0; j < 8; j++)
            #pragma unroll
            for (int r = 0; r < 4; r++) sacc[j][r] = 0.f;

        #pragma unroll
        for (int ks = 0; ks < 8; ks++) {
            const int k8 = ks * 8;
            unsigned a[4];
            a[0] = Qs[wm + g    ][k8 + q];
            a[1] = Qs[wm + g + 8][k8 + q];
            a[2] = Qs[wm + g    ][k8 + q + 4];
            a[3] = Qs[wm + g + 8][k8 + q + 4];
            const int s0 = 4 * ks;
            const int s1 = 4 * ks + 2;
            #pragma unroll
            for (int j = 0; j < 8; j++) {
                unsigned bb[2];
                bb[0] = Ks[k8 + q    ][(j * 8 + g) ^ s0];
                bb[1] = Ks[k8 + q + 4][(j * 8 + g) ^ s1];
                mma_tf32(sacc[j], a, bb);
            }
        }

        float mx0 = -1e30f, mx1 = -1e30f;
        #pragma unroll
        for (int j = 0; j < 8; j++) {
            mx0 = fmaxf(mx0, fmaxf(sacc[j][0], sacc[j][1]));
            mx1 = fmaxf(mx1, fmaxf(sacc[j][2], sacc[j][3]));
        }
        mx0 = fmaxf(mx0, __shfl_xor_sync(0xffffffffu, mx0, 1));
        mx0 = fmaxf(mx0, __shfl_xor_sync(0xffffffffu, mx0, 2));
        mx1 = fmaxf(mx1, __shfl_xor_sync(0xffffffffu, mx1, 1));
        mx1 = fmaxf(mx1, __shfl_xor_sync(0xffffffffu, mx1, 2));

        const float mnew0 = fmaxf(m0, mx0 * 0.125f);
        const float mnew1 = fmaxf(m1, mx1 * 0.125f);
        const float alpha0 = __expf(m0 - mnew0);
        const float alpha1 = __expf(m1 - mnew1);
        l0 *= alpha0;
        l1 *= alpha1;

        #pragma unroll
        for (int j = 0; j < 8; j++) {
            const int c0 = j * 8 + 2 * q;
            const float p00 = __expf(sacc[j][0] * 0.125f - mnew0);
            const float p01 = __expf(sacc[j][1] * 0.125f - mnew0);
            const float p10 = __expf(sacc[j][2] * 0.125f - mnew1);
            const float p11 = __expf(sacc[j][3] * 0.125f - mnew1);
            l0 += p00 + p01;
            l1 += p10 + p11;
            Ps[wm + g    ][c0    ] = f2tf32(p00);
            Ps[wm + g    ][c0 + 1] = f2tf32(p01);
            Ps[wm + g + 8][c0    ] = f2tf32(p10);
            Ps[wm + g + 8][c0 + 1] = f2tf32(p11);
            oacc[j][0] *= alpha0; oacc[j][1] *= alpha0;
            oacc[j][2] *= alpha1; oacc[j][3] *= alpha1;
        }
        m0 = mnew0; m1 = mnew1;
        __syncwarp();

        #pragma unroll
        for (int ks = 0; ks < 8; ks++) {
            const int k8 = ks * 8;
            unsigned a[4];
            a[0] = Ps[wm + g    ][k8 + q];
            a[1] = Ps[wm + g + 8][k8 + q];
            a[2] = Ps[wm + g    ][k8 + q + 4];
            a[3] = Ps[wm + g + 8][k8 + q + 4];
            #pragma unroll
            for (int j = 0; j < 8; j++) {
                unsigned bb[2];
                bb[0] = Vs[k8 + q    ][j * 8 + g];
                bb[1] = Vs[k8 + q + 4][j * 8 + g];
                mma_tf32(oacc[j], a, bb);
            }
        }
        __syncwarp();
    }

    l0 += __shfl_xor_sync(0xffffffffu, l0, 1);
    l0 += __shfl_xor_sync(0xffffffffu, l0, 2);
    l1 += __shfl_xor_sync(0xffffffffu, l1, 1);
    l1 += __shfl_xor_sync(0xffffffffu, l1, 2);
    const float inv0 = 1.0f / l0;
    const float inv1 = 1.0f / l1;

    const size_t row0 = (size_t)(b * SEQ + q0 + wm + g);
    #pragma unroll
    for (int j = 0; j < 8; j++) {
        const int c0 = h * HDIM + j * 8 + 2 * q;
        float2 w0; w0.x = oacc[j][0] * inv0; w0.y = oacc[j][1] * inv0;
        float2 w1; w1.x = oacc[j][2] * inv1; w1.y = oacc[j][3] * inv1;
        *reinterpret_cast<float2*>(O + row0 * CH + c0)       = w0;
        *reinterpret_cast<float2*>(O + (row0 + 8) * CH + c0) = w1;
    }
}

// ---------------------------------------------------------------------------
// Host-side orchestration
// ---------------------------------------------------------------------------
static void run_gemm_plain(const float* A, const float* B, float* C, int M, int N, int K)
{
    dim3 grid(N / 128, M / 128);
    gemm_tf32_kernel<0, false><<<grid, 256, GS_SMEM>>>(A, B, C, nullptr, nullptr, M, N, K);
}
static void run_gemm_bias_res(const float* A, const float* B, float* C,
                              const float* bias, const float* resid, int M, int N, int K)
{
    dim3 grid(N / 128, M / 128);
    gemm_tf32_kernel<1, true><<<grid, 256, GS_SMEM>>>(A, B, C, bias, resid, M, N, K);
}
static void run_gemm_bias_gelu(const float* A, const float* B, float* C,
                               const float* bias, int M, int N, int K)
{
    dim3 grid(N / 128, M / 128);
    gemm_tf32_kernel<2, false><<<grid, 256, GS_SMEM>>>(A, B, C, bias, nullptr, M, N, K);
}

extern "C" void kernel_launch(void* const* d_in, const int* in_sizes, int n_in,
                              void* d_out, int out_size)
{
    const float* x1    = (const float*)d_in[0];
    const float* x2    = (const float*)d_in[1];
    const float* x3    = (const float*)d_in[2];
    const float* ln11g = (const float*)d_in[3];
    const float* ln11b = (const float*)d_in[4];
    const float* ln12g = (const float*)d_in[5];
    const float* ln12b = (const float*)d_in[6];
    const float* ln21g = (const float*)d_in[7];
    const float* ln21b = (const float*)d_in[8];
    const float* ln23g = (const float*)d_in[9];
    const float* ln23b = (const float*)d_in[10];
    const float* ln2g  = (const float*)d_in[11];
    const float* ln2b  = (const float*)d_in[12];
    const float* a1wq  = (const float*)d_in[13];
    const float* a1wk  = (const float*)d_in[14];
    const float* a1wv  = (const float*)d_in[15];
    const float* a1wp  = (const float*)d_in[16];
    const float* a1bp  = (const float*)d_in[17];
    const float* a2wq  = (const float*)d_in[18];
    const float* a2wk  = (const float*)d_in[19];
    const float* a2wv  = (const float*)d_in[20];
    const float* a2wp  = (const float*)d_in[21];
    const float* a2bp  = (const float*)d_in[22];
    const float* fc1w  = (const float*)d_in[23];
    const float* fc1b  = (const float*)d_in[24];
    const float* fc2w  = (const float*)d_in[25];
    const float* fc2b  = (const float*)d_in[26];
    float* out = (float*)d_out;

    float *lnq, *lnkv, *q, *k, *v, *o, *x, *hbuf;
    cudaGetSymbolAddress((void**)&lnq,  g_lnq);
    cudaGetSymbolAddress((void**)&lnkv, g_lnkv);
    cudaGetSymbolAddress((void**)&q,    g_q);
    cudaGetSymbolAddress((void**)&k,    g_k);
    cudaGetSymbolAddress((void**)&v,    g_v);
    cudaGetSymbolAddress((void**)&o,    g_o);
    cudaGetSymbolAddress((void**)&x,    g_x);
    cudaGetSymbolAddress((void**)&hbuf, g_h);

    cudaFuncSetAttribute(attn_tf32_kernel, cudaFuncAttributeMaxDynamicSharedMemorySize,
                         (int)ATT2_SMEM);
    cudaFuncSetAttribute(gemm_tf32_kernel<0, false>, cudaFuncAttributeMaxDynamicSharedMemorySize,
                         (int)GS_SMEM);
    cudaFuncSetAttribute(gemm_tf32_kernel<1, true>,  cudaFuncAttributeMaxDynamicSharedMemorySize,
                         (int)GS_SMEM);
    cudaFuncSetAttribute(gemm_tf32_kernel<2, false>, cudaFuncAttributeMaxDynamicSharedMemorySize,
                         (int)GS_SMEM);

    const dim3 attn_grid(SEQ / 64, NHEAD, BATCH);

    // lnq2 = LN21(x1) parked in g_h (free until the MLP GEMM)
    float* lnq2 = hbuf;

    // ---- branch 1: cross-attn(LN11(x1), LN12(x2)) ----
    ln_dual_kernel<<<ROWS, 256>>>(x1, ln11g, ln11b, lnq, ln21g, ln21b, lnq2);
    ln_kernel<<<ROWS, 256>>>(x2, ln12g, ln12b, lnkv);
    run_gemm_plain(lnq,  a1wq, q, ROWS, CH, CH);
    run_gemm_plain(lnkv, a1wk, k, ROWS, CH, CH);
    run_gemm_plain(lnkv, a1wv, v, ROWS, CH, CH);
    attn_tf32_kernel<<<attn_grid, 128, ATT2_SMEM>>>(q, k, v, o);
    run_gemm_bias_res(o, a1wp, x, a1bp, x1, ROWS, CH, CH);   // x = x1 + br1

    // ---- branch 2: cross-attn(LN21(x1), LN23(x3)) ----
    ln_kernel<<<ROWS, 256>>>(x3, ln23g, ln23b, lnkv);
    run_gemm_plain(lnq2, a2wq, q, ROWS, CH, CH);
    run_gemm_plain(lnkv, a2wk, k, ROWS, CH, CH);
    run_gemm_plain(lnkv, a2wv, v, ROWS, CH, CH);
    attn_tf32_kernel<<<attn_grid, 128, ATT2_SMEM>>>(q, k, v, o);
    run_gemm_bias_res(o, a2wp, x, a2bp, x, ROWS, CH, CH);    // x += br2 (in-place resid)

    // ---- MLP ----
    ln_kernel<<<ROWS, 256>>>(x, ln2g, ln2b, lnq);
    run_gemm_bias_gelu(lnq, fc1w, hbuf, fc1b, ROWS, HID, CH);   // h = gelu(y@fc1+b1)
    run_gemm_bias_res(hbuf, fc2w, out, fc2b, x, ROWS, CH, HID); // out = x + h@fc2+b2
}